// round 3
// baseline (speedup 1.0000x reference)
#include <cuda_runtime.h>
#include <cuda_bf16.h>

// out[b, i] = x[b, i] * weight[i] + bias[i]
// BATCH = 8192, IN_SIZE = 4096, fp32. HBM-bound (268 MB/launch).
//
// R3 design: persistent single-wave kernel.
//  - grid = (4 col-groups, 256) = 1024 CTAs (~7/SM, one wave)
//  - each thread: fixed column, w/b in registers for the whole run
//  - grid-stride loop over rows, 4 rows/iter, loads front-batched
//  - no wave transitions, continuous load stream

static constexpr int IN_SIZE   = 4096;
static constexpr int IN_SIZE4  = IN_SIZE / 4;        // 1024 float4 per row
static constexpr int THREADS   = 256;
static constexpr int COL_GRPS  = IN_SIZE4 / THREADS; // 4
static constexpr int ROW_BLKS  = 256;                // grid.y
static constexpr int UNROLL    = 4;                  // rows per iteration

__global__ __launch_bounds__(THREADS)
void diag_linear_kernel(const float4* __restrict__ x4,
                        const float4* __restrict__ w4,
                        const float4* __restrict__ b4,
                        float4* __restrict__ out4,
                        int rows)
{
    const int col4 = blockIdx.x * THREADS + threadIdx.x;   // 0..1023

    // Loaded once per thread for the whole kernel
    const float4 wv = __ldg(&w4[col4]);
    const float4 bv = __ldg(&b4[col4]);

    const int  rstride = ROW_BLKS * UNROLL;                // 1024 rows/step
    const long lstride = (long)rstride * IN_SIZE4;

    long base = (long)(blockIdx.y * UNROLL) * IN_SIZE4 + col4;

    // rows = 8192 -> exactly 8 iterations, no tail
    for (int row = blockIdx.y * UNROLL; row < rows; row += rstride, base += lstride) {
        float4 v0 = __ldcs(&x4[base + 0L * IN_SIZE4]);
        float4 v1 = __ldcs(&x4[base + 1L * IN_SIZE4]);
        float4 v2 = __ldcs(&x4[base + 2L * IN_SIZE4]);
        float4 v3 = __ldcs(&x4[base + 3L * IN_SIZE4]);

        v0.x = fmaf(v0.x, wv.x, bv.x); v0.y = fmaf(v0.y, wv.y, bv.y);
        v0.z = fmaf(v0.z, wv.z, bv.z); v0.w = fmaf(v0.w, wv.w, bv.w);

        v1.x = fmaf(v1.x, wv.x, bv.x); v1.y = fmaf(v1.y, wv.y, bv.y);
        v1.z = fmaf(v1.z, wv.z, bv.z); v1.w = fmaf(v1.w, wv.w, bv.w);

        v2.x = fmaf(v2.x, wv.x, bv.x); v2.y = fmaf(v2.y, wv.y, bv.y);
        v2.z = fmaf(v2.z, wv.z, bv.z); v2.w = fmaf(v2.w, wv.w, bv.w);

        v3.x = fmaf(v3.x, wv.x, bv.x); v3.y = fmaf(v3.y, wv.y, bv.y);
        v3.z = fmaf(v3.z, wv.z, bv.z); v3.w = fmaf(v3.w, wv.w, bv.w);

        __stcs(&out4[base + 0L * IN_SIZE4], v0);
        __stcs(&out4[base + 1L * IN_SIZE4], v1);
        __stcs(&out4[base + 2L * IN_SIZE4], v2);
        __stcs(&out4[base + 3L * IN_SIZE4], v3);
    }
}

extern "C" void kernel_launch(void* const* d_in, const int* in_sizes, int n_in,
                              void* d_out, int out_size)
{
    const float* x      = (const float*)d_in[0];
    const float* weight = (const float*)d_in[1];
    const float* bias   = (const float*)d_in[2];
    float* out          = (float*)d_out;

    const int n    = in_sizes[0];        // BATCH * IN_SIZE
    const int rows = n / IN_SIZE;        // 8192

    dim3 grid(COL_GRPS, ROW_BLKS);       // (4, 256) = 1024 CTAs, ~1 wave
    diag_linear_kernel<<<grid, THREADS>>>(
        (const float4*)x, (const float4*)weight, (const float4*)bias,
        (float4*)out, rows);
}

// round 4
// speedup vs baseline: 1.1404x; 1.1404x over previous
#include <cuda_runtime.h>
#include <cuda_bf16.h>

// out[b, i] = x[b, i] * weight[i] + bias[i]
// BATCH = 8192, IN_SIZE = 4096, fp32. HBM-bound (268 MB/launch).
//
// R4 design: R2 shape (short CTAs, front-batched loads), MLP_p1 = 8.
//  - block = 256 threads, fixed strip of 256 float4 columns
//  - 8 rows per block, all 8 LDG.128 issued back-to-back
//  - grid = (4, 1024) = 4096 CTAs, no loop, no tail

static constexpr int IN_SIZE   = 4096;
static constexpr int IN_SIZE4  = IN_SIZE / 4;        // 1024 float4 per row
static constexpr int THREADS   = 256;
static constexpr int COL_GRPS  = IN_SIZE4 / THREADS; // 4
static constexpr int ROWS_PER_BLOCK = 8;

__global__ __launch_bounds__(THREADS)
void diag_linear_kernel(const float4* __restrict__ x4,
                        const float4* __restrict__ w4,
                        const float4* __restrict__ b4,
                        float4* __restrict__ out4)
{
    const int col4 = blockIdx.x * THREADS + threadIdx.x;      // 0..1023
    const int row0 = blockIdx.y * ROWS_PER_BLOCK;

    const float4 wv = __ldg(&w4[col4]);
    const float4 bv = __ldg(&b4[col4]);

    const long base = (long)row0 * IN_SIZE4 + col4;

    // 8 independent LDG.128 front-batched
    float4 v0 = __ldcs(&x4[base + 0L * IN_SIZE4]);
    float4 v1 = __ldcs(&x4[base + 1L * IN_SIZE4]);
    float4 v2 = __ldcs(&x4[base + 2L * IN_SIZE4]);
    float4 v3 = __ldcs(&x4[base + 3L * IN_SIZE4]);
    float4 v4 = __ldcs(&x4[base + 4L * IN_SIZE4]);
    float4 v5 = __ldcs(&x4[base + 5L * IN_SIZE4]);
    float4 v6 = __ldcs(&x4[base + 6L * IN_SIZE4]);
    float4 v7 = __ldcs(&x4[base + 7L * IN_SIZE4]);

    v0.x = fmaf(v0.x, wv.x, bv.x); v0.y = fmaf(v0.y, wv.y, bv.y);
    v0.z = fmaf(v0.z, wv.z, bv.z); v0.w = fmaf(v0.w, wv.w, bv.w);
    __stcs(&out4[base + 0L * IN_SIZE4], v0);

    v1.x = fmaf(v1.x, wv.x, bv.x); v1.y = fmaf(v1.y, wv.y, bv.y);
    v1.z = fmaf(v1.z, wv.z, bv.z); v1.w = fmaf(v1.w, wv.w, bv.w);
    __stcs(&out4[base + 1L * IN_SIZE4], v1);

    v2.x = fmaf(v2.x, wv.x, bv.x); v2.y = fmaf(v2.y, wv.y, bv.y);
    v2.z = fmaf(v2.z, wv.z, bv.z); v2.w = fmaf(v2.w, wv.w, bv.w);
    __stcs(&out4[base + 2L * IN_SIZE4], v2);

    v3.x = fmaf(v3.x, wv.x, bv.x); v3.y = fmaf(v3.y, wv.y, bv.y);
    v3.z = fmaf(v3.z, wv.z, bv.z); v3.w = fmaf(v3.w, wv.w, bv.w);
    __stcs(&out4[base + 3L * IN_SIZE4], v3);

    v4.x = fmaf(v4.x, wv.x, bv.x); v4.y = fmaf(v4.y, wv.y, bv.y);
    v4.z = fmaf(v4.z, wv.z, bv.z); v4.w = fmaf(v4.w, wv.w, bv.w);
    __stcs(&out4[base + 4L * IN_SIZE4], v4);

    v5.x = fmaf(v5.x, wv.x, bv.x); v5.y = fmaf(v5.y, wv.y, bv.y);
    v5.z = fmaf(v5.z, wv.z, bv.z); v5.w = fmaf(v5.w, wv.w, bv.w);
    __stcs(&out4[base + 5L * IN_SIZE4], v5);

    v6.x = fmaf(v6.x, wv.x, bv.x); v6.y = fmaf(v6.y, wv.y, bv.y);
    v6.z = fmaf(v6.z, wv.z, bv.z); v6.w = fmaf(v6.w, wv.w, bv.w);
    __stcs(&out4[base + 6L * IN_SIZE4], v6);

    v7.x = fmaf(v7.x, wv.x, bv.x); v7.y = fmaf(v7.y, wv.y, bv.y);
    v7.z = fmaf(v7.z, wv.z, bv.z); v7.w = fmaf(v7.w, wv.w, bv.w);
    __stcs(&out4[base + 7L * IN_SIZE4], v7);
}

extern "C" void kernel_launch(void* const* d_in, const int* in_sizes, int n_in,
                              void* d_out, int out_size)
{
    const float* x      = (const float*)d_in[0];
    const float* weight = (const float*)d_in[1];
    const float* bias   = (const float*)d_in[2];
    float* out          = (float*)d_out;

    const int n    = in_sizes[0];            // BATCH * IN_SIZE
    const int rows = n / IN_SIZE;            // 8192

    dim3 grid(COL_GRPS, rows / ROWS_PER_BLOCK);   // (4, 1024) = 4096 CTAs
    diag_linear_kernel<<<grid, THREADS>>>(
        (const float4*)x, (const float4*)weight, (const float4*)bias,
        (float4*)out);
}